// round 12
// baseline (speedup 1.0000x reference)
#include <cuda_runtime.h>
#include <math.h>

// Problem constants
#define NPTS   2048
#define NNODES 8192
#define NCMP   1024
#define NWORDS 256           // NNODES / 32
#define THRESH 2.2f          // tier-2 threshold (mean ~114 cands/row total)
#define T1     3.0f          // tier-1 threshold (mean ~11.1 cands/row)
#define T1CAP  64            // tier-1 capacity (P(cnt1>64) ~ 0)
#define T2CAP  160           // tier-2 capacity (mean ~103, sigma ~10)
#define CAP    (T1CAP + T2CAP)   // 224 slots/row

// Scratch (__device__ globals). g_bits is w-major: g_bits[w][c].
__device__ unsigned int       g_bits[NWORDS * NCMP];      // 1 MB
__device__ unsigned long long g_cand[(size_t)NPTS * CAP]; // {val:hi32, idx:lo32}; tier1 @0, tier2 @T1CAP
__device__ int2               g_cnt12[NPTS];              // {cnt1, cnt2}; -1 = overflow

// ---------------------------------------------------------------------------
// Fused kernel A+B (R9 form — measured ~18us). Grid 2560: bid%5==4 -> pack
// block (512, interleaved to overlap B); else select block (one row each).
// Select: lane-private two-tier classification, unordered scatter via smem
// atomic counters. No sort — kernel C max-combines, so order is irrelevant.
// ---------------------------------------------------------------------------
__global__ __launch_bounds__(256) void ab_kernel(const float* __restrict__ x,
                                                 const int* __restrict__ mask) {
    int bid = blockIdx.x;
    if ((bid % 5) == 4) {
        // ---- pack block (R2 form, measured best) ----
        int warp = threadIdx.x >> 5;
        int lane = threadIdx.x & 31;
        int task = (bid / 5) * 8 + warp;   // 0..4095
        int w    = task >> 4;
        int cg   = task & 15;
        int c0   = cg * 64 + lane * 2;
        int n0   = w * 32;

        unsigned b0 = 0, b1 = 0;
        const int* base = mask + (size_t)n0 * NCMP + c0;
        #pragma unroll
        for (int i = 0; i < 32; i++) {
            int2 v = *(const int2*)(base + (size_t)i * NCMP);
            b0 |= (unsigned)(v.x != 0) << i;
            b1 |= (unsigned)(v.y != 0) << i;
        }
        uint2 o; o.x = b0; o.y = b1;
        *(uint2*)(g_bits + (size_t)w * NCMP + c0) = o;
        return;
    }

    // ---- select block ----
    __shared__ int s_c1, s_c2;

    int p   = bid - bid / 5;               // 0..2047
    int tid = threadIdx.x;
    if (tid == 0) { s_c1 = 0; s_c2 = 0; }
    __syncthreads();

    unsigned long long* cand = g_cand + (size_t)p * CAP;
    const float4* row4 = (const float4*)(x + (size_t)p * NNODES);
    #pragma unroll
    for (int i = 0; i < NNODES / (256 * 4); i++) {       // 8 passes
        int q = tid + 256 * i;
        float4 v = row4[q];
        float m = fmaxf(fmaxf(v.x, v.y), fmaxf(v.z, v.w));
        if (m > THRESH) {                                // ~1.7 lanes/warp-pass
            int n = q * 4;
            #define HANDLE(comp, nn)                                              \
                if ((comp) > THRESH) {                                            \
                    unsigned long long e =                                        \
                        ((unsigned long long)__float_as_uint(comp) << 32) |       \
                        (unsigned)(nn);                                           \
                    if ((comp) > T1) {                                            \
                        int pos = atomicAdd(&s_c1, 1);                            \
                        if (pos < T1CAP) cand[pos] = e;                           \
                    } else {                                                      \
                        int pos = atomicAdd(&s_c2, 1);                            \
                        if (pos < T2CAP) cand[T1CAP + pos] = e;                   \
                    }                                                             \
                }
            HANDLE(v.x, n) HANDLE(v.y, n + 1) HANDLE(v.z, n + 2) HANDLE(v.w, n + 3)
            #undef HANDLE
        }
    }
    __syncthreads();

    if (tid == 0) {
        int c1 = s_c1, c2 = s_c2;
        int2 o;
        o.x = (c1 > T1CAP) ? -1 : c1;      // tier-1 overflow -> full fallback
        o.y = (c2 > T2CAP) ? -1 : c2;      // tier-2 overflow -> fallback if t1 missed
        g_cnt12[p] = o;
    }
}

// ---------------------------------------------------------------------------
// Kernel C: masked column max by max-combining over candidate hits.
// Shared bitset tile RESTORED (probes are LDS — the R9 global-probe version
// thrashed L1). Block = 32 columns x 64 rows: smem 40.7KB -> 5 CTAs/SM and
// 1024 blocks. Tier-1 (first 16/row staged in smem, rest from L2, ~5% of
// rows) -> tier-2 sweep (~1.4% of warp-rows) -> full bitset scan (rare;
// also yields 0.0 for empty columns). Max-combine is order-free and
// additive, so every stage just folds into res.
// ---------------------------------------------------------------------------
#define TC    32
#define TPR   64
#define STAGE 16

__global__ __launch_bounds__(256) void masked_colmax_kernel(const float* __restrict__ x,
                                                            float* __restrict__ out) {
    __shared__ unsigned int       s_bits[NWORDS * TC];   // 32 KB, [w][cl]
    __shared__ unsigned long long s_cs[TPR * STAGE];     // 8 KB
    __shared__ int2               s_cnt[TPR];            // 512 B

    int c0 = blockIdx.x * TC;
    int p0 = blockIdx.y * TPR;

    for (int i = threadIdx.x; i < NWORDS * (TC / 4); i += 256) {
        int w  = i >> 3;
        int cq = (i & 7) * 4;
        *(uint4*)(s_bits + w * TC + cq) =
            *(const uint4*)(g_bits + (size_t)w * NCMP + c0 + cq);
    }
    if (threadIdx.x < TPR) s_cnt[threadIdx.x] = g_cnt12[p0 + threadIdx.x];
    #pragma unroll
    for (int k = 0; k < (TPR * STAGE) / 256; k++) {      // 4 passes, coalesced
        int idx  = threadIdx.x + 256 * k;
        int r    = idx >> 4;
        int slot = idx & (STAGE - 1);
        s_cs[idx] = g_cand[(size_t)(p0 + r) * CAP + slot];
    }
    __syncthreads();

    int cl = threadIdx.x & 31;
    int pr = threadIdx.x >> 5;

    for (int r = pr; r < TPR; r += 8) {
        int p = p0 + r;
        int2 cc = s_cnt[r];                              // warp-uniform
        int cnt1 = cc.x, cnt2 = cc.y;
        float res = -INFINITY;

        // PROBE: test candidate e against this lane's column (LDS), fold max.
        #define PROBE(e, live)                                                    \
            {                                                                     \
                unsigned _i = (unsigned)(e) & (NNODES - 1);                       \
                bool _h = (live) &&                                               \
                    ((s_bits[(_i >> 5) * TC + cl] >> (_i & 31u)) & 1u);           \
                res = fmaxf(res, _h ? __uint_as_float((unsigned)((e) >> 32))      \
                                    : -INFINITY);                                 \
            }

        if (cnt1 >= 0) {
            const unsigned long long* cs = s_cs + r * STAGE;
            int ns = cnt1 < STAGE ? cnt1 : STAGE;
            #pragma unroll 1
            for (int k = 0; k < ns; k += 4) {            // 4 independent LDS probes
                unsigned long long e0 = cs[k], e1 = cs[k + 1];
                unsigned long long e2 = cs[k + 2], e3 = cs[k + 3];
                PROBE(e0, true) PROBE(e1, k + 1 < ns) PROBE(e2, k + 2 < ns) PROBE(e3, k + 3 < ns)
            }
            const unsigned long long* cg = g_cand + (size_t)p * CAP;
            #pragma unroll 1
            for (int k = STAGE; k < cnt1; k += 4) {      // P(cnt1>16) ~ 5%
                unsigned long long e0 = cg[k], e1 = cg[k + 1];
                unsigned long long e2 = cg[k + 2], e3 = cg[k + 3];
                PROBE(e0, true) PROBE(e1, k + 1 < cnt1) PROBE(e2, k + 2 < cnt1) PROBE(e3, k + 3 < cnt1)
            }
        }

        if (__any_sync(0xFFFFFFFFu, res == -INFINITY)) {
            if (cnt1 >= 0 && cnt2 >= 0) {                // tier-2 sweep (~1.4%)
                const unsigned long long* cg = g_cand + (size_t)p * CAP + T1CAP;
                #pragma unroll 1
                for (int k = 0; k < cnt2; k += 4) {
                    unsigned long long e0 = cg[k], e1 = cg[k + 1];
                    unsigned long long e2 = cg[k + 2], e3 = cg[k + 3];
                    PROBE(e0, true) PROBE(e1, k + 1 < cnt2) PROBE(e2, k + 2 < cnt2) PROBE(e3, k + 3 < cnt2)
                }
            }
            if (__any_sync(0xFFFFFFFFu, res == -INFINITY)) {
                // Full exact scan (overflow rows / all-miss / empty columns).
                const float* row = x + (size_t)p * NNODES;
                for (int w = 0; w < NWORDS; w++) {
                    unsigned int b = s_bits[w * TC + cl];
                    while (b) {
                        int bit = __ffs(b) - 1;
                        res = fmaxf(res, row[w * 32 + bit]);
                        b &= b - 1;
                    }
                }
            }
        }
        #undef PROBE

        out[(size_t)p * NCMP + (c0 + cl)] = (res == -INFINITY) ? 0.0f : res;
    }
}

// ---------------------------------------------------------------------------
extern "C" void kernel_launch(void* const* d_in, const int* in_sizes, int n_in,
                              void* d_out, int out_size) {
    const float* x;
    const int*   mask;
    if (in_sizes[0] == NPTS * NNODES) {    // metadata order: x, learned_edge_states
        x    = (const float*)d_in[0];
        mask = (const int*)d_in[1];
    } else {
        x    = (const float*)d_in[1];
        mask = (const int*)d_in[0];
    }
    float* out = (float*)d_out;

    ab_kernel<<<2560, 256>>>(x, mask);     // pack + tiered select, overlapped
    masked_colmax_kernel<<<dim3(NCMP / TC, NPTS / TPR), 256>>>(x, out);
}

// round 16
// speedup vs baseline: 3.3941x; 3.3941x over previous
#include <cuda_runtime.h>
#include <math.h>

// Problem constants
#define NPTS   2048
#define NNODES 8192
#define NCMP   1024
#define NWORDS 256           // NNODES / 32
#define CAP    96            // candidates/row (T=2.6 -> mean ~38, sigma ~6.2; 9.3 sigma)
#define THRESH 2.6f

// Scratch (__device__ globals). g_bits is w-major: g_bits[w][c].
__device__ unsigned int       g_bits[NWORDS * NCMP];      // 1 MB
__device__ unsigned long long g_cand[(size_t)NPTS * CAP]; // {val:hi32, idx:lo32}, descending
__device__ int                g_cnt[NPTS];                // count per row, -1 = overflow

// ---------------------------------------------------------------------------
// Fused kernel A+B. Grid 2560: bid%5==4 -> pack block (512, interleaved so
// pack's DRAM stream overlaps B's issue phase); else select block (one row).
//
// Pack: mask (int32 [N,C] row-major) -> w-major bitsets (R2 form, best).
// Select: lane-private hit path (atomicAdd + stores, no ballots), then a now-
// small O(nc^2) rank sort (nc~38) with (value,index) total order ->
// deterministic descending candidate list.
// ---------------------------------------------------------------------------
__global__ __launch_bounds__(256) void ab_kernel(const float* __restrict__ x,
                                                 const int* __restrict__ mask) {
    int bid = blockIdx.x;
    if ((bid % 5) == 4) {
        // ---- pack block ----
        int warp = threadIdx.x >> 5;
        int lane = threadIdx.x & 31;
        int task = (bid / 5) * 8 + warp;   // 0..4095
        int w    = task >> 4;
        int cg   = task & 15;
        int c0   = cg * 64 + lane * 2;
        int n0   = w * 32;

        unsigned b0 = 0, b1 = 0;
        const int* base = mask + (size_t)n0 * NCMP + c0;
        #pragma unroll
        for (int i = 0; i < 32; i++) {
            int2 v = *(const int2*)(base + (size_t)i * NCMP);
            b0 |= (unsigned)(v.x != 0) << i;
            b1 |= (unsigned)(v.y != 0) << i;
        }
        uint2 o; o.x = b0; o.y = b1;
        *(uint2*)(g_bits + (size_t)w * NCMP + c0) = o;   // coalesced 256B/warp
        return;
    }

    // ---- select block ----
    __shared__ float s_val[CAP];
    __shared__ int   s_idx[CAP];
    __shared__ int   s_cnt;

    int p   = bid - bid / 5;               // 0..2047
    int tid = threadIdx.x;
    if (tid == 0) s_cnt = 0;
    __syncthreads();

    const float4* row4 = (const float4*)(x + (size_t)p * NNODES);
    #pragma unroll
    for (int i = 0; i < NNODES / (256 * 4); i++) {       // 8 passes, loads hoisted
        int q = tid + 256 * i;
        float4 v = row4[q];
        float m = fmaxf(fmaxf(v.x, v.y), fmaxf(v.z, v.w));
        if (m > THRESH) {                                // ~0.6 lanes/warp-pass
            int n = q * 4;
            int cnt = (v.x > THRESH) + (v.y > THRESH) + (v.z > THRESH) + (v.w > THRESH);
            int pos = atomicAdd(&s_cnt, cnt);
            if (v.x > THRESH) { if (pos < CAP) { s_val[pos] = v.x; s_idx[pos] = n;     } pos++; }
            if (v.y > THRESH) { if (pos < CAP) { s_val[pos] = v.y; s_idx[pos] = n + 1; } pos++; }
            if (v.z > THRESH) { if (pos < CAP) { s_val[pos] = v.z; s_idx[pos] = n + 2; } pos++; }
            if (v.w > THRESH) { if (pos < CAP) { s_val[pos] = v.w; s_idx[pos] = n + 3; } pos++; }
        }
    }
    __syncthreads();

    int nc = s_cnt;
    if (nc > CAP) {                                      // overflow -> exact fallback in C
        if (tid == 0) g_cnt[p] = -1;
        return;
    }
    if (tid == 0) g_cnt[p] = nc;

    if (tid < nc) {                                      // nc ~ 38: cheap rank sort
        float fv = s_val[tid];
        int   id = s_idx[tid];
        int rank = 0;
        for (int j = 0; j < nc; j++) {
            float vj = s_val[j];
            rank += (vj > fv) || (vj == fv && s_idx[j] < id);
        }
        g_cand[(size_t)p * CAP + rank] =
            ((unsigned long long)__float_as_uint(fv) << 32) | (unsigned int)id;
    }
}

// ---------------------------------------------------------------------------
// Kernel C (R8 form — measured 23us): masked column max via descending-
// candidate early exit. Shared staging: row counts + first 16 candidates per
// row; probe chain is pure LDS for 99.95% of warp-rows (P(lane needs >16
// sorted candidates) = 2^-16). Block = 32 columns x 128 rows; bitset tile
// [w][cl] bank-clean and coalesced to load.
// ---------------------------------------------------------------------------
#define TC    32
#define TPR   128
#define STAGE 16

__global__ __launch_bounds__(256) void masked_colmax_kernel(const float* __restrict__ x,
                                                            float* __restrict__ out) {
    __shared__ unsigned int       s_bits[NWORDS * TC];   // 32 KB
    __shared__ unsigned long long s_cs[TPR * STAGE];     // 16 KB
    __shared__ int                s_rcnt[TPR];           // 512 B

    int c0 = blockIdx.x * TC;
    int p0 = blockIdx.y * TPR;

    for (int i = threadIdx.x; i < NWORDS * (TC / 4); i += 256) {
        int w  = i >> 3;
        int cq = (i & 7) * 4;
        *(uint4*)(s_bits + w * TC + cq) =
            *(const uint4*)(g_bits + (size_t)w * NCMP + c0 + cq);
    }
    if (threadIdx.x < TPR) s_rcnt[threadIdx.x] = g_cnt[p0 + threadIdx.x];
    #pragma unroll
    for (int k = 0; k < (TPR * STAGE) / 256; k++) {      // 8 passes, coalesced
        int idx  = threadIdx.x + 256 * k;                // 0..2047
        int r    = idx >> 4;
        int slot = idx & (STAGE - 1);
        s_cs[idx] = g_cand[(size_t)(p0 + r) * CAP + slot];  // 128B/row contiguous
    }
    __syncthreads();

    int cl = threadIdx.x & 31;
    int pr = threadIdx.x >> 5;

    for (int r = pr; r < TPR; r += 8) {
        int p   = p0 + r;
        int cnt = s_rcnt[r];                             // LDS broadcast
        float res = 0.0f;
        bool found = false;
        if (cnt >= 0) {
            const unsigned long long* cs = s_cs + r * STAGE;
            // Two batches of 8 from shared (early exit after each).
            #pragma unroll
            for (int base = 0; base < STAGE && !found; base += 8) {
                #define PROBE(j)                                                  \
                    unsigned long long e##j = cs[base + j];                       \
                    unsigned idx##j = (unsigned)e##j & (NNODES - 1);              \
                    float v##j = __uint_as_float((unsigned)(e##j >> 32));         \
                    bool h##j = (base + j < cnt) &&                               \
                        ((s_bits[(idx##j >> 5) * TC + cl] >> (idx##j & 31u)) & 1u);
                PROBE(0) PROBE(1) PROBE(2) PROBE(3)
                PROBE(4) PROBE(5) PROBE(6) PROBE(7)
                #undef PROBE
                // first hit (smallest j) wins: assign in descending j order
                if (h7) res = v7; if (h6) res = v6; if (h5) res = v5; if (h4) res = v4;
                if (h3) res = v3; if (h2) res = v2; if (h1) res = v1; if (h0) res = v0;
                found = h0 | h1 | h2 | h3 | h4 | h5 | h6 | h7;
            }
            // Deeper batches from global (p ~ 5e-4 per warp-row).
            const ulonglong2* cand2 = (const ulonglong2*)(g_cand + (size_t)p * CAP);
            #pragma unroll 1
            for (int base = STAGE; base < cnt && !found; base += 8) {
                int b2 = base >> 1;
                ulonglong2 e0 = cand2[b2 + 0];
                ulonglong2 e1 = cand2[b2 + 1];
                ulonglong2 e2 = cand2[b2 + 2];
                ulonglong2 e3 = cand2[b2 + 3];
                #define HIT(e, j, hv, vv)                                         \
                    unsigned gidx##j = (unsigned)(e) & (NNODES - 1);              \
                    float vv = __uint_as_float((unsigned)((e) >> 32));            \
                    bool hv = (base + j < cnt) &&                                 \
                        ((s_bits[(gidx##j >> 5) * TC + cl] >> (gidx##j & 31u)) & 1u);
                HIT(e0.x, 0, g0, w0) HIT(e0.y, 1, g1, w1)
                HIT(e1.x, 2, g2, w2) HIT(e1.y, 3, g3, w3)
                HIT(e2.x, 4, g4, w4) HIT(e2.y, 5, g5, w5)
                HIT(e3.x, 6, g6, w6) HIT(e3.y, 7, g7, w7)
                #undef HIT
                if (g7) res = w7; if (g6) res = w6; if (g5) res = w5; if (g4) res = w4;
                if (g3) res = w3; if (g2) res = w2; if (g1) res = w1; if (g0) res = w0;
                found = g0 | g1 | g2 | g3 | g4 | g5 | g6 | g7;
            }
        }
        if (!found) {
            // Exact fallback (overflow rows / no candidate masked / empty col).
            float m = -INFINITY;
            const float* row = x + (size_t)p * NNODES;
            for (int w = 0; w < NWORDS; w++) {
                unsigned int b = s_bits[w * TC + cl];
                while (b) {
                    int bit = __ffs(b) - 1;
                    m = fmaxf(m, row[w * 32 + bit]);
                    b &= b - 1;
                }
            }
            res = (m == -INFINITY) ? 0.0f : m;           // empty column -> 0.0
        }
        out[(size_t)p * NCMP + (c0 + cl)] = res;
    }
}

// ---------------------------------------------------------------------------
extern "C" void kernel_launch(void* const* d_in, const int* in_sizes, int n_in,
                              void* d_out, int out_size) {
    const float* x;
    const int*   mask;
    if (in_sizes[0] == NPTS * NNODES) {    // metadata order: x, learned_edge_states
        x    = (const float*)d_in[0];
        mask = (const int*)d_in[1];
    } else {
        x    = (const float*)d_in[1];
        mask = (const int*)d_in[0];
    }
    float* out = (float*)d_out;

    ab_kernel<<<2560, 256>>>(x, mask);     // pack + select fused/overlapped
    masked_colmax_kernel<<<dim3(NCMP / TC, NPTS / TPR), 256>>>(x, out);
}

// round 17
// speedup vs baseline: 4.0000x; 1.1785x over previous
#include <cuda_runtime.h>
#include <math.h>

// Problem constants
#define NPTS   2048
#define NNODES 8192
#define NCMP   1024
#define NCW    32            // NCMP / 32 column-words
#define CAP    96            // candidates/row (T=2.6 -> mean ~38, sigma ~6.2)
#define THRESH 2.6f

// Scratch (__device__ globals).
// g_cbits[cw][n]: bit b = (mask[n][cw*32+b] != 0)  — node-major per column-word.
__device__ unsigned int   g_cbits[NCW * NNODES];        // 1 MB
__device__ float          g_cval[(size_t)NPTS * CAP];   // sorted descending values
__device__ unsigned short g_cidx[(size_t)NPTS * CAP];   // matching node indices
__device__ int            g_cnt[NPTS];                  // count per row, -1 = overflow

// ---------------------------------------------------------------------------
// Fused kernel A+B. Grid 2304: bid%9==8 -> pack block (256, interleaved);
// else select block (one row each, 2048).
//
// Pack block: 32 nodes. Warp handles 4 nodes; per node, 32 coalesced 128B
// loads of the mask row + 32 ballots -> staged in shared -> coalesced 128B
// stores into the transposed g_cbits layout.
//
// Select: 8 float4 loads hoisted (MLP=8), lane-private threshold scatter,
// then O(nc^2) rank sort (nc~38) with (value,index) total order ->
// deterministic descending candidate list split into value/index arrays.
// ---------------------------------------------------------------------------
__global__ __launch_bounds__(256) void ab_kernel(const float* __restrict__ x,
                                                 const int* __restrict__ mask) {
    __shared__ unsigned s_buf[2 * CAP + 1 > 1024 ? 2 * CAP + 1 : 1024];

    int bid = blockIdx.x;
    if ((bid % 9) == 8) {
        // ---- pack block: nodes n0..n0+31, transposed bitset ----
        unsigned* s_t = s_buf;             // s_t[cw*32 + nl]
        int blk  = bid / 9;                // 0..255
        int n0   = blk * 32;
        int warp = threadIdx.x >> 5;
        int lane = threadIdx.x & 31;

        #pragma unroll
        for (int j = 0; j < 4; j++) {
            int nl = warp * 4 + j;
            const int* rowm = mask + (size_t)(n0 + nl) * NCMP + lane;
            #pragma unroll
            for (int g = 0; g < 4; g++) {  // cw groups of 8 (MLP=8 loads)
                int v0 = rowm[(g * 8 + 0) * 32];
                int v1 = rowm[(g * 8 + 1) * 32];
                int v2 = rowm[(g * 8 + 2) * 32];
                int v3 = rowm[(g * 8 + 3) * 32];
                int v4 = rowm[(g * 8 + 4) * 32];
                int v5 = rowm[(g * 8 + 5) * 32];
                int v6 = rowm[(g * 8 + 6) * 32];
                int v7 = rowm[(g * 8 + 7) * 32];
                unsigned b;
                b = __ballot_sync(0xFFFFFFFFu, v0 != 0); if (lane == 0) s_t[(g*8+0)*32 + nl] = b;
                b = __ballot_sync(0xFFFFFFFFu, v1 != 0); if (lane == 0) s_t[(g*8+1)*32 + nl] = b;
                b = __ballot_sync(0xFFFFFFFFu, v2 != 0); if (lane == 0) s_t[(g*8+2)*32 + nl] = b;
                b = __ballot_sync(0xFFFFFFFFu, v3 != 0); if (lane == 0) s_t[(g*8+3)*32 + nl] = b;
                b = __ballot_sync(0xFFFFFFFFu, v4 != 0); if (lane == 0) s_t[(g*8+4)*32 + nl] = b;
                b = __ballot_sync(0xFFFFFFFFu, v5 != 0); if (lane == 0) s_t[(g*8+5)*32 + nl] = b;
                b = __ballot_sync(0xFFFFFFFFu, v6 != 0); if (lane == 0) s_t[(g*8+6)*32 + nl] = b;
                b = __ballot_sync(0xFFFFFFFFu, v7 != 0); if (lane == 0) s_t[(g*8+7)*32 + nl] = b;
            }
        }
        __syncthreads();
        #pragma unroll
        for (int k = 0; k < 4; k++) {      // coalesced 128B per warp
            int idx = threadIdx.x + 256 * k;
            int cw  = idx >> 5;
            int i   = idx & 31;
            g_cbits[(size_t)cw * NNODES + n0 + i] = s_t[idx];
        }
        return;
    }

    // ---- select block ----
    float* s_val = (float*)s_buf;
    int*   s_idx = (int*)(s_buf + CAP);
    int*   s_cnt = (int*)(s_buf + 2 * CAP);

    int p   = (bid / 9) * 8 + (bid % 9);   // 0..2047
    int tid = threadIdx.x;
    if (tid == 0) *s_cnt = 0;
    __syncthreads();

    const float4* row4 = (const float4*)(x + (size_t)p * NNODES);
    float4 v[8];
    #pragma unroll
    for (int i = 0; i < 8; i++) v[i] = row4[tid + 256 * i];   // MLP=8, hoisted

    #pragma unroll
    for (int i = 0; i < 8; i++) {
        float4 a = v[i];
        float m = fmaxf(fmaxf(a.x, a.y), fmaxf(a.z, a.w));
        if (m > THRESH) {                  // ~0.6 lanes/warp-pass
            int n = (tid + 256 * i) * 4;
            int cnt = (a.x > THRESH) + (a.y > THRESH) + (a.z > THRESH) + (a.w > THRESH);
            int pos = atomicAdd(s_cnt, cnt);
            if (a.x > THRESH) { if (pos < CAP) { s_val[pos] = a.x; s_idx[pos] = n;     } pos++; }
            if (a.y > THRESH) { if (pos < CAP) { s_val[pos] = a.y; s_idx[pos] = n + 1; } pos++; }
            if (a.z > THRESH) { if (pos < CAP) { s_val[pos] = a.z; s_idx[pos] = n + 2; } pos++; }
            if (a.w > THRESH) { if (pos < CAP) { s_val[pos] = a.w; s_idx[pos] = n + 3; } pos++; }
        }
    }
    __syncthreads();

    int nc = *s_cnt;
    if (nc > CAP) {                        // overflow -> exact fallback in C
        if (tid == 0) g_cnt[p] = -1;
        return;
    }
    if (tid == 0) g_cnt[p] = nc;

    if (tid < nc) {                        // nc ~ 38: cheap rank sort
        float fv = s_val[tid];
        int   id = s_idx[tid];
        int rank = 0;
        for (int j = 0; j < nc; j++) {
            float vj = s_val[j];
            rank += (vj > fv) || (vj == fv && s_idx[j] < id);
        }
        g_cval[(size_t)p * CAP + rank] = fv;
        g_cidx[(size_t)p * CAP + rank] = (unsigned short)id;
    }
}

// ---------------------------------------------------------------------------
// Kernel C: masked column max via descending-candidate early exit, broadcast
// probes. Block = one column-word (32 columns) x 128 rows. Tile s_cb[n] =
// g_cbits[cw][n] (CONTIGUOUS 32KB load). Probe = broadcast LDS; lane cl takes
// bit cl. 8 probes -> hitmask -> ffs -> one value LDS. Deep candidates from
// global (11.8% of warp-rows); full exact scan fallback (~0 prob + overflow/
// empty -> 0.0).
// ---------------------------------------------------------------------------
#define TC  32
#define TPR 128

__global__ __launch_bounds__(256) void masked_colmax_kernel(const float* __restrict__ x,
                                                            float* __restrict__ out) {
    __shared__ unsigned s_cb[NNODES];                        // 32 KB
    __shared__ __align__(16) unsigned short s_ci[TPR * 8];   // 2 KB
    __shared__ __align__(16) float          s_cv[TPR * 8];   // 4 KB
    __shared__ int s_rcnt[TPR];                              // 512 B

    int cw = blockIdx.x;                   // column word 0..31
    int c0 = cw * 32;
    int p0 = blockIdx.y * TPR;

    {   // contiguous, fully coalesced tile load
        const uint4* src = (const uint4*)(g_cbits + (size_t)cw * NNODES);
        uint4* dst = (uint4*)s_cb;
        #pragma unroll
        for (int k = 0; k < NNODES / 4 / 256; k++)
            dst[threadIdx.x + 256 * k] = src[threadIdx.x + 256 * k];
    }
    if (threadIdx.x < TPR) {
        s_rcnt[threadIdx.x] = g_cnt[p0 + threadIdx.x];
        *(uint4*)(s_ci + threadIdx.x * 8) =
            *(const uint4*)(g_cidx + (size_t)(p0 + threadIdx.x) * CAP);
    }
    {
        int r = threadIdx.x >> 1, h = threadIdx.x & 1;
        *(uint4*)(s_cv + r * 8 + h * 4) =
            *(const uint4*)(g_cval + (size_t)(p0 + r) * CAP + h * 4);
    }
    __syncthreads();

    int cl = threadIdx.x & 31;
    int pr = threadIdx.x >> 5;

    for (int r = pr; r < TPR; r += 8) {
        int p   = p0 + r;
        int cnt = s_rcnt[r];               // warp-uniform
        uint4 I = *(const uint4*)(s_ci + r * 8);   // 8 indices, one broadcast LDS.128
        unsigned i0 = I.x & 0x1FFFu, i1 = (I.x >> 16) & 0x1FFFu;
        unsigned i2 = I.y & 0x1FFFu, i3 = (I.y >> 16) & 0x1FFFu;
        unsigned i4 = I.z & 0x1FFFu, i5 = (I.z >> 16) & 0x1FFFu;
        unsigned i6 = I.w & 0x1FFFu, i7 = (I.w >> 16) & 0x1FFFu;
        unsigned hm = 0;
        hm += ((s_cb[i0] >> cl) & 1u);         // broadcast probes
        hm += ((s_cb[i1] >> cl) & 1u) << 1;
        hm += ((s_cb[i2] >> cl) & 1u) << 2;
        hm += ((s_cb[i3] >> cl) & 1u) << 3;
        hm += ((s_cb[i4] >> cl) & 1u) << 4;
        hm += ((s_cb[i5] >> cl) & 1u) << 5;
        hm += ((s_cb[i6] >> cl) & 1u) << 6;
        hm += ((s_cb[i7] >> cl) & 1u) << 7;
        unsigned live = (cnt >= 8) ? 0xFFu : (cnt > 0 ? ((1u << cnt) - 1u) : 0u);
        unsigned valid = hm & live;

        float res = 0.0f;
        bool found = false;
        if (valid) {                       // first (largest) hit = masked max
            int k = __ffs(valid) - 1;
            res = s_cv[r * 8 + k];         // <=8 distinct banks -> conflict-free
            found = true;
        }

        if (__any_sync(0xFFFFFFFFu, !found)) {
            // Deeper sorted candidates from global, batches of 4.
            for (int k = 8; k < cnt && __any_sync(0xFFFFFFFFu, !found); k += 4) {
                ushort4 ii = *(const ushort4*)(g_cidx + (size_t)p * CAP + k);
                float4  vv = *(const float4*) (g_cval + (size_t)p * CAP + k);
                bool h0 = !found && (k + 0 < cnt) && ((s_cb[ii.x & 0x1FFFu] >> cl) & 1u);
                bool h1 = !found && (k + 1 < cnt) && ((s_cb[ii.y & 0x1FFFu] >> cl) & 1u);
                bool h2 = !found && (k + 2 < cnt) && ((s_cb[ii.z & 0x1FFFu] >> cl) & 1u);
                bool h3 = !found && (k + 3 < cnt) && ((s_cb[ii.w & 0x1FFFu] >> cl) & 1u);
                if (h3) res = vv.w; if (h2) res = vv.z; if (h1) res = vv.y; if (h0) res = vv.x;
                found = found | h0 | h1 | h2 | h3;
            }
            if (__any_sync(0xFFFFFFFFu, !found)) {
                // Exact full scan (overflow / cnt==0 / all-miss; empty -> 0.0).
                if (!found) {
                    float m = -INFINITY;
                    const float* row = x + (size_t)p * NNODES;
                    for (int n = 0; n < NNODES; n++) {
                        if ((s_cb[n] >> cl) & 1u) m = fmaxf(m, row[n]);
                    }
                    res = (m == -INFINITY) ? 0.0f : m;
                }
            }
        }
        out[(size_t)p * NCMP + (c0 + cl)] = res;
    }
}

// ---------------------------------------------------------------------------
extern "C" void kernel_launch(void* const* d_in, const int* in_sizes, int n_in,
                              void* d_out, int out_size) {
    const float* x;
    const int*   mask;
    if (in_sizes[0] == NPTS * NNODES) {    // metadata order: x, learned_edge_states
        x    = (const float*)d_in[0];
        mask = (const int*)d_in[1];
    } else {
        x    = (const float*)d_in[1];
        mask = (const int*)d_in[0];
    }
    float* out = (float*)d_out;

    ab_kernel<<<2304, 256>>>(x, mask);     // pack(transposed) + select, overlapped
    masked_colmax_kernel<<<dim3(NCW, NPTS / TPR), 256>>>(x, out);
}